// round 9
// baseline (speedup 1.0000x reference)
#include <cuda_runtime.h>
#include <cuda_bf16.h>
#include <math.h>
#include <stdint.h>

#define NH    32
#define LLEN  4096
#define BSTRIDE 144   // bytes per b-row in smem B (64 bf16 + 16B pad)

struct C2 { float r, i; };

static __device__ __forceinline__ C2 cmul(C2 a, C2 b) {
    return { a.r * b.r - a.i * b.i, a.r * b.i + a.i * b.r };
}

// fp32 phase reduction: exact Dekker product + 3-term Cody-Waite (R6-proven)
static __device__ __forceinline__ float reduce2pi(float yi, float lf) {
    const float INV2PI = 0.15915494309189534f;
    const float PI2_A  = 6.28125f;
    const float PI2_B  = 1.93500518798828125e-3f;
    const float PI2_C  = 3.0199159819568e-7f;
    const float p  = yi * lf;
    const float pe = fmaf(yi, lf, -p);
    const float k  = rintf(p * INV2PI);
    const float t0 = fmaf(-k, PI2_A, p);
    const float t1 = fmaf(-k, PI2_B, t0);
    return fmaf(-k, PI2_C, t1) + pe;
}

static __device__ __forceinline__ C2 zpow(float xr, float yi, float lf) {
    const float red = reduce2pi(yi, lf);
    float sf, cf;
    __sincosf(red, &sf, &cf);
    const float ef = __expf(xr * lf);
    return { ef * cf, ef * sf };
}

static __device__ __forceinline__ void split_pack(float v0, float v1,
                                                  uint32_t& hi, uint32_t& lo) {
    __nv_bfloat16 h0 = __float2bfloat16(v0);
    __nv_bfloat16 h1 = __float2bfloat16(v1);
    __nv_bfloat16 l0 = __float2bfloat16(v0 - __bfloat162float(h0));
    __nv_bfloat16 l1 = __float2bfloat16(v1 - __bfloat162float(h1));
    __nv_bfloat162 hp = __halves2bfloat162(h0, h1);
    __nv_bfloat162 lp = __halves2bfloat162(l0, l1);
    hi = *reinterpret_cast<uint32_t*>(&hp);
    lo = *reinterpret_cast<uint32_t*>(&lp);
}

static __device__ __forceinline__ void mma16816(
    float& d0, float& d1, float& d2, float& d3,
    uint32_t a0, uint32_t a1, uint32_t a2, uint32_t a3,
    uint32_t b0, uint32_t b1)
{
    asm volatile(
        "mma.sync.aligned.m16n8k16.row.col.f32.bf16.bf16.f32 "
        "{%0,%1,%2,%3}, {%4,%5,%6,%7}, {%8,%9}, {%0,%1,%2,%3};"
        : "+f"(d0), "+f"(d1), "+f"(d2), "+f"(d3)
        : "r"(a0), "r"(a1), "r"(a2), "r"(a3), "r"(b0), "r"(b1));
}

__global__ __launch_bounds__(256, 3) void s4d_mma_kernel(
    const float* __restrict__ log_dt,
    const float* __restrict__ C_real,
    const float* __restrict__ log_A_real,
    const float* __restrict__ A_imag,
    float* __restrict__ out)
{
    __shared__ float sxr[NH], syi[NH], scdr[NH], scdi[NH];
    __shared__ float sz8r[NH], sz8i[NH], szbr[NH], szbi[NH];   // z^8, z^2048
    // B (hi,lo) [b][k] bf16 rows of 144B; overlaid later by Dt[64][68] f32
    __shared__ __align__(16) unsigned char sB[2 * 64 * BSTRIDE];   // 18432 B

    const int h   = blockIdx.x;
    const int tid = threadIdx.x;

    // ---- phase 1: per-n scalars (warp 0) -------------------------------------
    if (tid < NH) {
        const int n = tid;
        const float dt  = expf(log_dt[h]);
        const float Arf = -expf(log_A_real[h * NH + n]);
        const float Aif = A_imag[h * NH + n];
        const float xr  = dt * Arf;          // matches reference f32 product
        const float yi  = dt * Aif;

        const float em1 = expm1f(xr);
        float sy, cy;
        sincosf(yi, &sy, &cy);
        const float sh   = sinf(0.5f * yi);
        const float numr = em1 * cy - 2.0f * sh * sh;   // e^x cos y - 1
        const float numi = (1.0f + em1) * sy;           // e^x sin y
        const float invd = 1.0f / (Arf * Arf + Aif * Aif);
        const float tr = (numr * Arf + numi * Aif) * invd;
        const float ti = (numi * Arf - numr * Aif) * invd;
        const float Cr = C_real[(h * NH + n) * 2 + 0];
        const float Ci = C_real[(h * NH + n) * 2 + 1];
        scdr[n] = 2.0f * (Cr * tr - Ci * ti);
        scdi[n] = 2.0f * (Cr * ti + Ci * tr);
        sxr[n] = xr;
        syi[n] = yi;
        C2 z8 = zpow(xr, yi, 8.0f);
        sz8r[n] = z8.r;  sz8i[n] = z8.i;
        C2 zb = zpow(xr, yi, 2048.0f);
        szbr[n] = zb.r;  szbi[n] = zb.i;
    }
    __syncthreads();

    // ---- B producer: thread -> (b=lane, b=lane+32) x 4 consecutive n ---------
    {
        const int bl = tid & 31;
        const int nb = (tid >> 5) * 4;     // 4 consecutive n -> one STS.128
        unsigned char* Bh = sB;
        unsigned char* Bl = sB + 64 * BSTRIDE;
        uint32_t h0v[4], l0v[4], h1v[4], l1v[4];
        #pragma unroll
        for (int j = 0; j < 4; j++) {
            const int n = nb + j;
            const float xr = sxr[n], yi = syi[n];
            const C2 q  = zpow(xr, yi, (float)(64 * bl));
            const C2 qh = cmul(q, C2{ szbr[n], szbi[n] });   // b + 32
            split_pack(q.r,  q.i,  h0v[j], l0v[j]);
            split_pack(qh.r, qh.i, h1v[j], l1v[j]);
        }
        const uint32_t off  = (uint32_t)(bl * BSTRIDE + 4 * nb);        // 16B aligned
        const uint32_t off2 = (uint32_t)((bl + 32) * BSTRIDE + 4 * nb);
        *(uint4*)(Bh + off)  = *(uint4*)h0v;
        *(uint4*)(Bl + off)  = *(uint4*)l0v;
        *(uint4*)(Bh + off2) = *(uint4*)h1v;
        *(uint4*)(Bl + off2) = *(uint4*)l1v;
    }

    // ---- A fragments in registers (mma layout) -------------------------------
    const int wid  = tid >> 5;
    const int wrow = wid & 3;      // row group: rows 16*wrow .. +15
    const int wcol = wid >> 2;     // 0: b 0-31, 1: b 32-63
    const int r = (tid >> 2) & 7;  // lane/4
    const int t = tid & 3;         // lane%4
    const float alo = (float)(16 * wrow + r);

    uint32_t Ah[4][4], Al[4][4];
    #pragma unroll
    for (int kt = 0; kt < 4; kt++) {
        #pragma unroll
        for (int s = 0; s < 2; s++) {
            const int n = 8 * kt + t + 4 * s;
            const C2 cd = { scdr[n], scdi[n] };
            const C2 z8 = { sz8r[n], sz8i[n] };
            const C2 wv = zpow(sxr[n], syi[n], alo);
            const C2 p  = cmul(cd, wv);        // row a
            const C2 ph = cmul(p, z8);         // row a+8
            split_pack(p.r,  -p.i,  Ah[kt][0 + 2 * s], Al[kt][0 + 2 * s]);
            split_pack(ph.r, -ph.i, Ah[kt][1 + 2 * s], Al[kt][1 + 2 * s]);
        }
    }
    __syncthreads();

    // ---- MMA mainloop: 4 n-tiles x 4 k-tiles x 3 split passes ----------------
    float d[4][4];
    #pragma unroll
    for (int nt = 0; nt < 4; nt++)
        #pragma unroll
        for (int c = 0; c < 4; c++) d[nt][c] = 0.0f;

    const unsigned char* Bh  = sB;
    const unsigned char* Blo = sB + 64 * BSTRIDE;
    #pragma unroll
    for (int nt = 0; nt < 4; nt++) {
        const int ntg = 4 * wcol + nt;
        const uint32_t rowoff = (uint32_t)((8 * ntg + r) * BSTRIDE + 4 * t);
        #pragma unroll
        for (int kt = 0; kt < 4; kt++) {
            const uint32_t off = rowoff + (uint32_t)(32 * kt);
            const uint32_t bh0 = *(const uint32_t*)(Bh  + off);
            const uint32_t bh1 = *(const uint32_t*)(Bh  + off + 16);
            const uint32_t bl0 = *(const uint32_t*)(Blo + off);
            const uint32_t bl1 = *(const uint32_t*)(Blo + off + 16);
            mma16816(d[nt][0], d[nt][1], d[nt][2], d[nt][3],
                     Ah[kt][0], Ah[kt][1], Ah[kt][2], Ah[kt][3], bh0, bh1);
            mma16816(d[nt][0], d[nt][1], d[nt][2], d[nt][3],
                     Ah[kt][0], Ah[kt][1], Ah[kt][2], Ah[kt][3], bl0, bl1);
            mma16816(d[nt][0], d[nt][1], d[nt][2], d[nt][3],
                     Al[kt][0], Al[kt][1], Al[kt][2], Al[kt][3], bh0, bh1);
        }
    }
    __syncthreads();   // all B reads done before Dt overlay

    // ---- stage D[a][b] -> Dt[b][a] (pad 68: conflict-free writes) ------------
    float (*Dt)[68] = reinterpret_cast<float(*)[68]>(sB);
    {
        const int ar = 16 * wrow + r;
        #pragma unroll
        for (int nt = 0; nt < 4; nt++) {
            const int bc = 8 * (4 * wcol + nt) + 2 * t;
            Dt[bc    ][ar    ] = d[nt][0];
            Dt[bc + 1][ar    ] = d[nt][1];
            Dt[bc    ][ar + 8] = d[nt][2];
            Dt[bc + 1][ar + 8] = d[nt][3];
        }
    }
    __syncthreads();

    // ---- coalesced vector store: out[h][b*64+a] ------------------------------
    float* outh = out + (size_t)h * LLEN;
    #pragma unroll
    for (int i = 0; i < 4; i++) {
        const int idx = i * 1024 + tid * 4;
        const float4 v = *(const float4*)&Dt[idx >> 6][idx & 63];
        *(float4*)&outh[idx] = v;
    }
}

extern "C" void kernel_launch(void* const* d_in, const int* in_sizes, int n_in,
                              void* d_out, int out_size)
{
    const float* log_dt     = (const float*)d_in[0];
    const float* C_real     = (const float*)d_in[1];
    const float* log_A_real = (const float*)d_in[2];
    const float* A_imag     = (const float*)d_in[3];
    float* out = (float*)d_out;
    s4d_mma_kernel<<<1024, 256>>>(log_dt, C_real, log_A_real, A_imag, out);
}

// round 11
// speedup vs baseline: 1.0985x; 1.0985x over previous
#include <cuda_runtime.h>
#include <cuda_bf16.h>
#include <math.h>
#include <stdint.h>

#define NH    32
#define LLEN  4096
#define BSTRIDE 144   // bytes per b-row in smem B (64 bf16 + 16B pad)

struct C2 { float r, i; };

static __device__ __forceinline__ C2 cmul(C2 a, C2 b) {
    return { a.r * b.r - a.i * b.i, a.r * b.i + a.i * b.r };
}

// fp32 phase reduction: exact Dekker product + 3-term Cody-Waite (R6-proven)
static __device__ __forceinline__ float reduce2pi(float yi, float lf) {
    const float INV2PI = 0.15915494309189534f;
    const float PI2_A  = 6.28125f;
    const float PI2_B  = 1.93500518798828125e-3f;
    const float PI2_C  = 3.0199159819568e-7f;
    const float p  = yi * lf;
    const float pe = fmaf(yi, lf, -p);
    const float k  = rintf(p * INV2PI);
    const float t0 = fmaf(-k, PI2_A, p);
    const float t1 = fmaf(-k, PI2_B, t0);
    return fmaf(-k, PI2_C, t1) + pe;
}

static __device__ __forceinline__ C2 zpow(float xr, float yi, float lf) {
    const float red = reduce2pi(yi, lf);
    float sf, cf;
    __sincosf(red, &sf, &cf);
    const float ef = __expf(xr * lf);
    return { ef * cf, ef * sf };
}

static __device__ __forceinline__ void split_pack(float v0, float v1,
                                                  uint32_t& hi, uint32_t& lo) {
    __nv_bfloat16 h0 = __float2bfloat16(v0);
    __nv_bfloat16 h1 = __float2bfloat16(v1);
    __nv_bfloat16 l0 = __float2bfloat16(v0 - __bfloat162float(h0));
    __nv_bfloat16 l1 = __float2bfloat16(v1 - __bfloat162float(h1));
    __nv_bfloat162 hp = __halves2bfloat162(h0, h1);
    __nv_bfloat162 lp = __halves2bfloat162(l0, l1);
    hi = *reinterpret_cast<uint32_t*>(&hp);
    lo = *reinterpret_cast<uint32_t*>(&lp);
}

static __device__ __forceinline__ void mma16816(
    float& d0, float& d1, float& d2, float& d3,
    uint32_t a0, uint32_t a1, uint32_t a2, uint32_t a3,
    uint32_t b0, uint32_t b1)
{
    asm volatile(
        "mma.sync.aligned.m16n8k16.row.col.f32.bf16.bf16.f32 "
        "{%0,%1,%2,%3}, {%4,%5,%6,%7}, {%8,%9}, {%0,%1,%2,%3};"
        : "+f"(d0), "+f"(d1), "+f"(d2), "+f"(d3)
        : "r"(a0), "r"(a1), "r"(a2), "r"(a3), "r"(b0), "r"(b1));
}

__global__ __launch_bounds__(128, 6) void s4d_mma_kernel(
    const float* __restrict__ log_dt,
    const float* __restrict__ C_real,
    const float* __restrict__ log_A_real,
    const float* __restrict__ A_imag,
    float* __restrict__ out)
{
    __shared__ float sxr[NH], syi[NH], scdr[NH], scdi[NH];
    // anchor tables: [0]=z^i, [1]=Cd*z^(8j), [2]=z^(64i), [3]=z^(512j)
    __shared__ __align__(16) float2 sTab[4][NH][8];                // 8 KB
    // B (hi,lo) [b][k] bf16 rows of 144B; overlaid later by Dt[64][68] f32
    __shared__ __align__(16) unsigned char sB[2 * 64 * BSTRIDE];   // 18432 B

    const int h   = blockIdx.x;
    const int tid = threadIdx.x;

    // ---- phase 1: per-n scalars (warp 0) -------------------------------------
    if (tid < NH) {
        const int n = tid;
        const float dt  = expf(log_dt[h]);
        const float Arf = -expf(log_A_real[h * NH + n]);
        const float Aif = A_imag[h * NH + n];
        const float xr  = dt * Arf;          // matches reference f32 product
        const float yi  = dt * Aif;

        const float em1 = expm1f(xr);
        float sy, cy;
        sincosf(yi, &sy, &cy);
        const float sh   = sinf(0.5f * yi);
        const float numr = em1 * cy - 2.0f * sh * sh;   // e^x cos y - 1
        const float numi = (1.0f + em1) * sy;           // e^x sin y
        const float invd = 1.0f / (Arf * Arf + Aif * Aif);
        const float tr = (numr * Arf + numi * Aif) * invd;
        const float ti = (numi * Arf - numr * Aif) * invd;
        const float Cr = C_real[(h * NH + n) * 2 + 0];
        const float Ci = C_real[(h * NH + n) * 2 + 1];
        scdr[n] = 2.0f * (Cr * tr - Ci * ti);
        scdi[n] = 2.0f * (Cr * ti + Ci * tr);
        sxr[n] = xr;
        syi[n] = yi;
    }
    __syncthreads();

    // ---- phase 2: anchor tables, 8 independent zpow per thread ---------------
    {
        #pragma unroll
        for (int q = 0; q < 8; q++) {
            const int f   = q * 128 + tid;     // 0..1023
            const int tab = f >> 8;            // 0..3
            const int sub = f & 255;
            const int n   = sub >> 3;
            const int i   = sub & 7;
            const int mul = (tab == 0) ? 1 : (tab == 1) ? 8 : (tab == 2) ? 64 : 512;
            C2 zv = zpow(sxr[n], syi[n], (float)(mul * i));
            if (tab == 1) zv = cmul(C2{ scdr[n], scdi[n] }, zv);
            sTab[tab][n][i] = make_float2(zv.r, zv.i);
        }
    }
    __syncthreads();

    // ---- B producer: thread -> (b=lane, b=lane+32) x 8 n, pure cmul ----------
    {
        const int bl = tid & 31;
        const int nb = (tid >> 5) * 8;
        const int bi = bl & 7;
        const int bj = bl >> 3;
        unsigned char* Bh = sB;
        unsigned char* Bl = sB + 64 * BSTRIDE;
        uint32_t h0v[8], l0v[8], h1v[8], l1v[8];
        #pragma unroll
        for (int j = 0; j < 8; j++) {
            const int n = nb + j;
            const float2 tc  = sTab[2][n][bi];
            const float2 td  = sTab[3][n][bj];
            const float2 td2 = sTab[3][n][bj + 4];
            const C2 q  = cmul(C2{ td.x,  td.y  }, C2{ tc.x, tc.y });  // z^(64*bl)
            const C2 qh = cmul(C2{ td2.x, td2.y }, C2{ tc.x, tc.y });  // z^(64*(bl+32))
            split_pack(q.r,  q.i,  h0v[j], l0v[j]);
            split_pack(qh.r, qh.i, h1v[j], l1v[j]);
        }
        const uint32_t off  = (uint32_t)(bl * BSTRIDE + 4 * nb);
        const uint32_t off2 = (uint32_t)((bl + 32) * BSTRIDE + 4 * nb);
        *(uint4*)(Bh + off)       = *(uint4*)(h0v);
        *(uint4*)(Bh + off + 16)  = *(uint4*)(h0v + 4);
        *(uint4*)(Bl + off)       = *(uint4*)(l0v);
        *(uint4*)(Bl + off + 16)  = *(uint4*)(l0v + 4);
        *(uint4*)(Bh + off2)      = *(uint4*)(h1v);
        *(uint4*)(Bh + off2 + 16) = *(uint4*)(h1v + 4);
        *(uint4*)(Bl + off2)      = *(uint4*)(l1v);
        *(uint4*)(Bl + off2 + 16) = *(uint4*)(l1v + 4);
    }

    // ---- A fragments in registers (mma layout), pure cmul from tables --------
    const int w = tid >> 5;        // warp -> rows 16w..16w+15
    const int r = (tid >> 2) & 7;  // lane/4
    const int t = tid & 3;         // lane%4

    uint32_t Ah[4][4], Al[4][4];
    #pragma unroll
    for (int kt = 0; kt < 4; kt++) {
        #pragma unroll
        for (int s = 0; s < 2; s++) {
            const int n = 8 * kt + t + 4 * s;
            const float2 ta  = sTab[0][n][r];          // z^r
            const float2 tb0 = sTab[1][n][2 * w];      // Cd*z^(16w)
            const float2 tb1 = sTab[1][n][2 * w + 1];  // Cd*z^(16w+8)
            const C2 p  = cmul(C2{ tb0.x, tb0.y }, C2{ ta.x, ta.y });  // Cd*z^a
            const C2 ph = cmul(C2{ tb1.x, tb1.y }, C2{ ta.x, ta.y });  // Cd*z^(a+8)
            split_pack(p.r,  -p.i,  Ah[kt][0 + 2 * s], Al[kt][0 + 2 * s]);
            split_pack(ph.r, -ph.i, Ah[kt][1 + 2 * s], Al[kt][1 + 2 * s]);
        }
    }
    __syncthreads();

    // ---- MMA mainloop: 8 n-tiles x 4 k-tiles x 3 split passes ----------------
    float d[8][4];
    #pragma unroll
    for (int nt = 0; nt < 8; nt++)
        #pragma unroll
        for (int c = 0; c < 4; c++) d[nt][c] = 0.0f;

    const unsigned char* Bh  = sB;
    const unsigned char* Blo = sB + 64 * BSTRIDE;
    #pragma unroll
    for (int nt = 0; nt < 8; nt++) {
        const uint32_t rowoff = (uint32_t)((8 * nt + r) * BSTRIDE + 4 * t);
        #pragma unroll
        for (int kt = 0; kt < 4; kt++) {
            const uint32_t off = rowoff + (uint32_t)(32 * kt);
            const uint32_t bh0 = *(const uint32_t*)(Bh  + off);
            const uint32_t bh1 = *(const uint32_t*)(Bh  + off + 16);
            const uint32_t bl0 = *(const uint32_t*)(Blo + off);
            const uint32_t bl1 = *(const uint32_t*)(Blo + off + 16);
            mma16816(d[nt][0], d[nt][1], d[nt][2], d[nt][3],
                     Ah[kt][0], Ah[kt][1], Ah[kt][2], Ah[kt][3], bh0, bh1);
            mma16816(d[nt][0], d[nt][1], d[nt][2], d[nt][3],
                     Ah[kt][0], Ah[kt][1], Ah[kt][2], Ah[kt][3], bl0, bl1);
            mma16816(d[nt][0], d[nt][1], d[nt][2], d[nt][3],
                     Al[kt][0], Al[kt][1], Al[kt][2], Al[kt][3], bh0, bh1);
        }
    }
    __syncthreads();   // all B reads done before Dt overlay

    // ---- stage D[a][b] -> Dt[b][a] (pad 68 words: conflict-free writes) ------
    float (*Dt)[68] = reinterpret_cast<float(*)[68]>(sB);
    {
        const int ar = 16 * w + r;
        #pragma unroll
        for (int nt = 0; nt < 8; nt++) {
            const int bc = 8 * nt + 2 * t;
            Dt[bc    ][ar    ] = d[nt][0];
            Dt[bc + 1][ar    ] = d[nt][1];
            Dt[bc    ][ar + 8] = d[nt][2];
            Dt[bc + 1][ar + 8] = d[nt][3];
        }
    }
    __syncthreads();

    // ---- coalesced vector store: out[h][b*64+a] ------------------------------
    float* outh = out + (size_t)h * LLEN;
    #pragma unroll
    for (int it = 0; it < 8; it++) {
        const int idx = it * 512 + tid * 4;
        const float4 v = *(const float4*)&Dt[idx >> 6][idx & 63];
        *(float4*)&outh[idx] = v;
    }
}

extern "C" void kernel_launch(void* const* d_in, const int* in_sizes, int n_in,
                              void* d_out, int out_size)
{
    const float* log_dt     = (const float*)d_in[0];
    const float* C_real     = (const float*)d_in[1];
    const float* log_A_real = (const float*)d_in[2];
    const float* A_imag     = (const float*)d_in[3];
    float* out = (float*)d_out;
    s4d_mma_kernel<<<1024, 128>>>(log_dt, C_real, log_A_real, A_imag, out);
}

// round 12
// speedup vs baseline: 1.1477x; 1.0447x over previous
#include <cuda_runtime.h>
#include <cuda_bf16.h>
#include <math.h>
#include <stdint.h>

#define NH    32
#define LLEN  4096
#define BSTRIDE 144   // bytes per b-row in smem B (64 bf16 + 16B pad)

struct C2 { float r, i; };

static __device__ __forceinline__ C2 cmul(C2 a, C2 b) {
    return { a.r * b.r - a.i * b.i, a.r * b.i + a.i * b.r };
}

// fp32 phase reduction: exact Dekker product + 3-term Cody-Waite (R6-proven)
static __device__ __forceinline__ float reduce2pi(float yi, float lf) {
    const float INV2PI = 0.15915494309189534f;
    const float PI2_A  = 6.28125f;
    const float PI2_B  = 1.93500518798828125e-3f;
    const float PI2_C  = 3.0199159819568e-7f;
    const float p  = yi * lf;
    const float pe = fmaf(yi, lf, -p);
    const float k  = rintf(p * INV2PI);
    const float t0 = fmaf(-k, PI2_A, p);
    const float t1 = fmaf(-k, PI2_B, t0);
    return fmaf(-k, PI2_C, t1) + pe;
}

static __device__ __forceinline__ C2 zpow(float xr, float yi, float lf) {
    const float red = reduce2pi(yi, lf);
    float sf, cf;
    __sincosf(red, &sf, &cf);
    const float ef = __expf(xr * lf);
    return { ef * cf, ef * sf };
}

// split (v0,v1) into bf16 hi pair + lo pair using packed cvt + bit-trick residual
static __device__ __forceinline__ void split_pack(float v0, float v1,
                                                  uint32_t& hi, uint32_t& lo) {
    uint32_t hp;
    asm("cvt.rn.bf16x2.f32 %0, %1, %2;" : "=r"(hp) : "f"(v1), "f"(v0)); // lo16=v0
    const float f0 = __uint_as_float(hp << 16);
    const float f1 = __uint_as_float(hp & 0xFFFF0000u);
    const float r0 = v0 - f0;
    const float r1 = v1 - f1;
    asm("cvt.rn.bf16x2.f32 %0, %1, %2;" : "=r"(lo) : "f"(r1), "f"(r0));
    hi = hp;
}

static __device__ __forceinline__ void mma16816(
    float& d0, float& d1, float& d2, float& d3,
    uint32_t a0, uint32_t a1, uint32_t a2, uint32_t a3,
    uint32_t b0, uint32_t b1)
{
    asm volatile(
        "mma.sync.aligned.m16n8k16.row.col.f32.bf16.bf16.f32 "
        "{%0,%1,%2,%3}, {%4,%5,%6,%7}, {%8,%9}, {%0,%1,%2,%3};"
        : "+f"(d0), "+f"(d1), "+f"(d2), "+f"(d3)
        : "r"(a0), "r"(a1), "r"(a2), "r"(a3), "r"(b0), "r"(b1));
}

__global__ __launch_bounds__(128, 8) void s4d_mma_kernel(
    const float* __restrict__ log_dt,
    const float* __restrict__ C_real,
    const float* __restrict__ log_A_real,
    const float* __restrict__ A_imag,
    float* __restrict__ out)
{
    __shared__ float sxr[NH], syi[NH], scdr[NH], scdi[NH];
    // anchor tables: [0]=z^i, [1]=Cd*z^(8j), [2]=z^(64i), [3]=z^(512j)
    __shared__ __align__(16) float2 sTab[4][NH][8];                // 8 KB
    // B (hi,lo) [b][k] bf16 rows of 144B; overlaid later by Dt[64][68] f32
    __shared__ __align__(16) unsigned char sB[2 * 64 * BSTRIDE];   // 18432 B

    const int h   = blockIdx.x;
    const int tid = threadIdx.x;

    // ---- phase 1: per-n scalars (warp 0) -------------------------------------
    if (tid < NH) {
        const int n = tid;
        const float dt  = expf(log_dt[h]);
        const float Arf = -expf(log_A_real[h * NH + n]);
        const float Aif = A_imag[h * NH + n];
        const float xr  = dt * Arf;          // matches reference f32 product
        const float yi  = dt * Aif;

        const float em1 = expm1f(xr);
        float sy, cy;
        sincosf(yi, &sy, &cy);
        const float sh   = sinf(0.5f * yi);
        const float numr = em1 * cy - 2.0f * sh * sh;   // e^x cos y - 1
        const float numi = (1.0f + em1) * sy;           // e^x sin y
        const float invd = 1.0f / (Arf * Arf + Aif * Aif);
        const float tr = (numr * Arf + numi * Aif) * invd;
        const float ti = (numi * Arf - numr * Aif) * invd;
        const float Cr = C_real[(h * NH + n) * 2 + 0];
        const float Ci = C_real[(h * NH + n) * 2 + 1];
        scdr[n] = 2.0f * (Cr * tr - Ci * ti);
        scdi[n] = 2.0f * (Cr * ti + Ci * tr);
        sxr[n] = xr;
        syi[n] = yi;
    }
    __syncthreads();

    // ---- phase 2: anchor tables, 8 independent zpow per thread ---------------
    {
        #pragma unroll
        for (int q = 0; q < 8; q++) {
            const int f   = q * 128 + tid;     // 0..1023
            const int tab = f >> 8;            // 0..3
            const int sub = f & 255;
            const int n   = sub >> 3;
            const int i   = sub & 7;
            const int mul = (tab == 0) ? 1 : (tab == 1) ? 8 : (tab == 2) ? 64 : 512;
            C2 zv = zpow(sxr[n], syi[n], (float)(mul * i));
            if (tab == 1) zv = cmul(C2{ scdr[n], scdi[n] }, zv);
            sTab[tab][n][i] = make_float2(zv.r, zv.i);
        }
    }
    __syncthreads();

    // ---- B producer: thread -> (b=lane, b=lane+32) x 8 n, pure cmul ----------
    {
        const int bl = tid & 31;
        const int nb = (tid >> 5) * 8;
        const int bi = bl & 7;
        const int bj = bl >> 3;
        unsigned char* Bh = sB;
        unsigned char* Bl = sB + 64 * BSTRIDE;
        uint32_t h0v[8], l0v[8], h1v[8], l1v[8];
        #pragma unroll
        for (int j = 0; j < 8; j++) {
            const int n = nb + j;
            const float2 tc  = sTab[2][n][bi];
            const float2 td  = sTab[3][n][bj];
            const float2 td2 = sTab[3][n][bj + 4];
            const C2 q  = cmul(C2{ td.x,  td.y  }, C2{ tc.x, tc.y });  // z^(64*bl)
            const C2 qh = cmul(C2{ td2.x, td2.y }, C2{ tc.x, tc.y });  // z^(64*(bl+32))
            split_pack(q.r,  q.i,  h0v[j], l0v[j]);
            split_pack(qh.r, qh.i, h1v[j], l1v[j]);
        }
        const uint32_t off  = (uint32_t)(bl * BSTRIDE + 4 * nb);
        const uint32_t off2 = (uint32_t)((bl + 32) * BSTRIDE + 4 * nb);
        *(uint4*)(Bh + off)       = *(uint4*)(h0v);
        *(uint4*)(Bh + off + 16)  = *(uint4*)(h0v + 4);
        *(uint4*)(Bl + off)       = *(uint4*)(l0v);
        *(uint4*)(Bl + off + 16)  = *(uint4*)(l0v + 4);
        *(uint4*)(Bh + off2)      = *(uint4*)(h1v);
        *(uint4*)(Bh + off2 + 16) = *(uint4*)(h1v + 4);
        *(uint4*)(Bl + off2)      = *(uint4*)(l1v);
        *(uint4*)(Bl + off2 + 16) = *(uint4*)(l1v + 4);
    }
    __syncthreads();

    // ---- MMA mainloop: kt outer (A frags live only per-kt -> low regs) -------
    const int w = tid >> 5;        // warp -> rows 16w..16w+15
    const int r = (tid >> 2) & 7;  // lane/4
    const int t = tid & 3;         // lane%4

    float d[8][4];
    #pragma unroll
    for (int nt = 0; nt < 8; nt++)
        #pragma unroll
        for (int c = 0; c < 4; c++) d[nt][c] = 0.0f;

    const unsigned char* Bh  = sB;
    const unsigned char* Blo = sB + 64 * BSTRIDE;

    #pragma unroll
    for (int kt = 0; kt < 4; kt++) {
        // A fragments for this kt from tables (2 cmul + 2 split per s)
        uint32_t Ah[4], Al[4];
        #pragma unroll
        for (int s = 0; s < 2; s++) {
            const int n = 8 * kt + t + 4 * s;
            const float2 ta  = sTab[0][n][r];          // z^r
            const float2 tb0 = sTab[1][n][2 * w];      // Cd*z^(16w)
            const float2 tb1 = sTab[1][n][2 * w + 1];  // Cd*z^(16w+8)
            const C2 p  = cmul(C2{ tb0.x, tb0.y }, C2{ ta.x, ta.y });  // Cd*z^a
            const C2 ph = cmul(C2{ tb1.x, tb1.y }, C2{ ta.x, ta.y });  // Cd*z^(a+8)
            split_pack(p.r,  -p.i,  Ah[0 + 2 * s], Al[0 + 2 * s]);
            split_pack(ph.r, -ph.i, Ah[1 + 2 * s], Al[1 + 2 * s]);
        }
        #pragma unroll
        for (int nt = 0; nt < 8; nt++) {
            const uint32_t off = (uint32_t)((8 * nt + r) * BSTRIDE + 4 * t + 32 * kt);
            const uint32_t bh0 = *(const uint32_t*)(Bh  + off);
            const uint32_t bh1 = *(const uint32_t*)(Bh  + off + 16);
            const uint32_t bl0 = *(const uint32_t*)(Blo + off);
            const uint32_t bl1 = *(const uint32_t*)(Blo + off + 16);
            mma16816(d[nt][0], d[nt][1], d[nt][2], d[nt][3],
                     Ah[0], Ah[1], Ah[2], Ah[3], bh0, bh1);
            mma16816(d[nt][0], d[nt][1], d[nt][2], d[nt][3],
                     Ah[0], Ah[1], Ah[2], Ah[3], bl0, bl1);
            mma16816(d[nt][0], d[nt][1], d[nt][2], d[nt][3],
                     Al[0], Al[1], Al[2], Al[3], bh0, bh1);
        }
    }
    __syncthreads();   // all B reads done before Dt overlay

    // ---- stage D[a][b] -> Dt[b][a] (pad 68 words: conflict-free writes) ------
    float (*Dt)[68] = reinterpret_cast<float(*)[68]>(sB);
    {
        const int ar = 16 * w + r;
        #pragma unroll
        for (int nt = 0; nt < 8; nt++) {
            const int bc = 8 * nt + 2 * t;
            Dt[bc    ][ar    ] = d[nt][0];
            Dt[bc + 1][ar    ] = d[nt][1];
            Dt[bc    ][ar + 8] = d[nt][2];
            Dt[bc + 1][ar + 8] = d[nt][3];
        }
    }
    __syncthreads();

    // ---- coalesced vector store: out[h][b*64+a] ------------------------------
    float* outh = out + (size_t)h * LLEN;
    #pragma unroll
    for (int it = 0; it < 8; it++) {
        const int idx = it * 512 + tid * 4;
        const float4 v = *(const float4*)&Dt[idx >> 6][idx & 63];
        *(float4*)&outh[idx] = v;
    }
}

extern "C" void kernel_launch(void* const* d_in, const int* in_sizes, int n_in,
                              void* d_out, int out_size)
{
    const float* log_dt     = (const float*)d_in[0];
    const float* C_real     = (const float*)d_in[1];
    const float* log_A_real = (const float*)d_in[2];
    const float* A_imag     = (const float*)d_in[3];
    float* out = (float*)d_out;
    s4d_mma_kernel<<<1024, 128>>>(log_dt, C_real, log_A_real, A_imag, out);
}